// round 10
// baseline (speedup 1.0000x reference)
#include <cuda_runtime.h>
#include <cstdint>

#define NNODES 50000
#define NEDGES 400000
#define FEAT   64
#define HEADS  4

// ---------------- scratch (static device globals; no allocation) ----------------
__device__ float g_Qp[(size_t)NNODES * 256];   // Q' = x @ M_h, layout [n][h*64+d]
__device__ float g_T [(size_t)NNODES * 256];   // segment-softmax-weighted sums of x_s
__device__ float g_M [HEADS * 64 * 64];        // M_h = Wq_h @ Wk_h^T * scale, [h][k][c]
__device__ float g_Wst[256 * 64];              // Wst[k][c] = (Wv@Wout)/4, k = h*64+f
__device__ uint4 g_BqpF[HEADS * 8 * 8 * 32];   // packed tf32 B frags for gemm_qp
__device__ uint4 g_WstF[32 * 8 * 32];          // packed tf32 B frags for gemm_out
__device__ int   g_deg   [NNODES];
__device__ int   g_rowptr[NNODES + 1];
__device__ int   g_cursor[NNODES];
__device__ int   g_esend [NEDGES];
__device__ int   g_bsum  [64];
__device__ int   g_bsumx [64];

// ---------------- tf32 helpers ----------------
__device__ __forceinline__ void f2tf32_split(float v, unsigned& hi, unsigned& lo) {
    asm("cvt.rna.tf32.f32 %0, %1;" : "=r"(hi) : "f"(v));
    float l = v - __uint_as_float(hi);
    asm("cvt.rna.tf32.f32 %0, %1;" : "=r"(lo) : "f"(l));
}

#define MMA_TF32(c, a0, a1, a2, a3, b0, b1)                                          \
    asm volatile(                                                                    \
        "mma.sync.aligned.m16n8k8.row.col.f32.tf32.tf32.f32 "                        \
        "{%0,%1,%2,%3}, {%4,%5,%6,%7}, {%8,%9}, {%0,%1,%2,%3};"                      \
        : "+f"((c)[0]), "+f"((c)[1]), "+f"((c)[2]), "+f"((c)[3])                     \
        : "r"(a0), "r"(a1), "r"(a2), "r"(a3), "r"(b0), "r"(b1))

// ---------------- small matrix prep ----------------
__global__ __launch_bounds__(256) void prep_mats_kernel(
    const float* __restrict__ Wq, const float* __restrict__ Wk,
    const float* __restrict__ Wv, const float* __restrict__ Wout)
{
    __shared__ float As[64 * 65];
    __shared__ float Bs[64 * 65];
    int b = blockIdx.x;
    int tid = threadIdx.x;

    if (b < 4) {
        int h = b;
        const float* A = Wq + h * 4096;
        const float* B = Wk + h * 4096;
        for (int i = tid; i < 4096; i += 256) {
            As[(i >> 6) * 65 + (i & 63)] = A[i];
            Bs[(i >> 6) * 65 + (i & 63)] = B[i];
        }
        __syncthreads();
        for (int o = tid; o < 4096; o += 256) {
            int f1 = o & 63, f2 = o >> 6;
            float s = 0.f;
            #pragma unroll 8
            for (int d = 0; d < 64; d++)
                s += As[f1 * 65 + d] * Bs[f2 * 65 + d];
            g_M[h * 4096 + f1 * 64 + f2] = s * 0.125f;
        }
    } else {
        int h = b - 4;
        const float* A = Wv + h * 4096;
        for (int i = tid; i < 4096; i += 256) {
            As[(i >> 6) * 65 + (i & 63)] = A[i];
            Bs[(i >> 6) * 65 + (i & 63)] = Wout[i];
        }
        __syncthreads();
        for (int o = tid; o < 4096; o += 256) {
            int f = o & 63, c = o >> 6;
            float s = 0.f;
            #pragma unroll 8
            for (int d = 0; d < 64; d++)
                s += As[f * 65 + d] * Bs[d * 65 + c];
            g_Wst[(h * 64 + f) * 64 + c] = s * 0.25f;
        }
    }
}

// pack B matrices into mma-fragment order with hi/lo tf32 split.
__global__ __launch_bounds__(256) void pack_frags_kernel() {
    int tid = blockIdx.x * 256 + threadIdx.x;
    if (tid < 8192) {
        int lane = tid & 31;
        int nt = (tid >> 5) & 7;
        int kt = (tid >> 8) & 7;
        int h  = tid >> 11;
        int k0 = kt * 8 + (lane & 3);
        int nn = nt * 8 + (lane >> 2);
        float v0 = g_M[h * 4096 + k0 * 64 + nn];
        float v1 = g_M[h * 4096 + (k0 + 4) * 64 + nn];
        uint4 o;
        f2tf32_split(v0, o.x, o.z);
        f2tf32_split(v1, o.y, o.w);
        g_BqpF[tid] = o;
    } else if (tid < 16384) {
        int t = tid - 8192;
        int lane = t & 31;
        int nt = (t >> 5) & 7;
        int kt = t >> 8;
        int k0 = kt * 8 + (lane & 3);
        int nn = nt * 8 + (lane >> 2);
        float v0 = g_Wst[k0 * 64 + nn];
        float v1 = g_Wst[(k0 + 4) * 64 + nn];
        uint4 o;
        f2tf32_split(v0, o.x, o.z);
        f2tf32_split(v1, o.y, o.w);
        g_WstF[t] = o;
    }
}

// ---------------- CSR build ----------------
__global__ void zero_deg_kernel(int n) {
    int i = blockIdx.x * blockDim.x + threadIdx.x;
    if (i < n) g_deg[i] = 0;
}

__global__ void count_deg_kernel(const int* __restrict__ recv, int E) {
    int i = blockIdx.x * blockDim.x + threadIdx.x;
    if (i < E) atomicAdd(&g_deg[recv[i]], 1);
}

__global__ __launch_bounds__(1024) void scan_blocks_kernel(int n) {
    __shared__ int wsum[32];
    int b = blockIdx.x;
    int tid = threadIdx.x, lane = tid & 31, wid = tid >> 5;
    int i = (b << 10) + tid;
    int v = (i < n) ? g_deg[i] : 0;
    int xi = v;
    #pragma unroll
    for (int o = 1; o < 32; o <<= 1) {
        int t = __shfl_up_sync(0xffffffffu, xi, o);
        if (lane >= o) xi += t;
    }
    if (lane == 31) wsum[wid] = xi;
    __syncthreads();
    if (wid == 0) {
        int s = wsum[lane];
        #pragma unroll
        for (int o = 1; o < 32; o <<= 1) {
            int t = __shfl_up_sync(0xffffffffu, s, o);
            if (lane >= o) s += t;
        }
        wsum[lane] = s;
    }
    __syncthreads();
    int incl = xi + (wid ? wsum[wid - 1] : 0);
    if (i < n) g_rowptr[i] = incl - v;
    if (tid == 1023) g_bsum[b] = incl;
}

__global__ __launch_bounds__(32) void scan_tops_kernel(int nb, int n) {
    int lane = threadIdx.x;
    int v0 = (lane < nb) ? g_bsum[lane] : 0;
    int v1 = (lane + 32 < nb) ? g_bsum[lane + 32] : 0;
    int s0 = v0;
    #pragma unroll
    for (int o = 1; o < 32; o <<= 1) {
        int t = __shfl_up_sync(0xffffffffu, s0, o);
        if (lane >= o) s0 += t;
    }
    int tot0 = __shfl_sync(0xffffffffu, s0, 31);
    int s1 = v1;
    #pragma unroll
    for (int o = 1; o < 32; o <<= 1) {
        int t = __shfl_up_sync(0xffffffffu, s1, o);
        if (lane >= o) s1 += t;
    }
    s1 += tot0;
    g_bsumx[lane] = s0 - v0;
    g_bsumx[lane + 32] = s1 - v1;
    if (lane == 31) g_rowptr[n] = s1;
}

__global__ __launch_bounds__(1024) void scan_add_kernel(int n) {
    int i = (blockIdx.x << 10) + threadIdx.x;
    if (i < n) {
        int r = g_rowptr[i] + g_bsumx[blockIdx.x];
        g_rowptr[i] = r;
        g_cursor[i] = r;
    }
}

__global__ void scatter_edges_kernel(const int* __restrict__ send,
                                     const int* __restrict__ recv, int E) {
    int i = blockIdx.x * blockDim.x + threadIdx.x;
    if (i < E) {
        int pos = atomicAdd(&g_cursor[recv[i]], 1);
        g_esend[pos] = send[i];
    }
}

// ---------------- GEMM 1: Q' = x @ M_h  (tensor cores, 3xTF32) ----------------
// 256 threads / 8 warps; warp = ONE 16-row m-tile (acc 32 regs -> high occupancy).
// x tile loaded once, reused across 4 heads; B frags LDG.128 from L2-hot arrays.
__global__ __launch_bounds__(256) void gemm_qp_kernel(const float* __restrict__ x, int n) {
    __shared__ float As[128][68];
    int row0 = blockIdx.x * 128;
    int tid = threadIdx.x, warp = tid >> 5, lane = tid & 31;
    int rq = lane >> 2, rr = lane & 3;
    int rb = (warp << 4) + rq;          // warp's m-tile rows: rb, rb+8

    for (int i = tid; i < 2048; i += 256) {
        int r = i >> 4, k4 = (i & 15) << 2;
        int gr = row0 + r;
        float4 v = make_float4(0.f, 0.f, 0.f, 0.f);
        if (gr < n) v = *reinterpret_cast<const float4*>(x + (size_t)gr * 64 + k4);
        *reinterpret_cast<float4*>(&As[r][k4]) = v;
    }
    __syncthreads();

    for (int h = 0; h < HEADS; h++) {
        float acc[8][4];
        #pragma unroll
        for (int nt = 0; nt < 8; nt++)
            #pragma unroll
            for (int q = 0; q < 4; q++) acc[nt][q] = 0.f;

        #pragma unroll
        for (int kt = 0; kt < 8; kt++) {
            int kb = (kt << 3) + rr;
            unsigned ah[4], al[4];
            f2tf32_split(As[rb][kb],         ah[0], al[0]);
            f2tf32_split(As[rb + 8][kb],     ah[1], al[1]);
            f2tf32_split(As[rb][kb + 4],     ah[2], al[2]);
            f2tf32_split(As[rb + 8][kb + 4], ah[3], al[3]);

            const uint4* Bf = g_BqpF + ((h * 8 + kt) * 8) * 32 + lane;
            #pragma unroll
            for (int nt = 0; nt < 8; nt++) {
                uint4 b = Bf[nt * 32];
                MMA_TF32(acc[nt], ah[0], ah[1], ah[2], ah[3], b.x, b.y);
                MMA_TF32(acc[nt], al[0], al[1], al[2], al[3], b.x, b.y);
                MMA_TF32(acc[nt], ah[0], ah[1], ah[2], ah[3], b.z, b.w);
            }
        }

        int r0 = row0 + rb;
        #pragma unroll
        for (int nt = 0; nt < 8; nt++) {
            int c = h * 64 + nt * 8 + rr * 2;
            if (r0 < n)
                *reinterpret_cast<float2*>(g_Qp + (size_t)r0 * 256 + c) =
                    make_float2(acc[nt][0], acc[nt][1]);
            if (r0 + 8 < n)
                *reinterpret_cast<float2*>(g_Qp + (size_t)(r0 + 8) * 256 + c) =
                    make_float2(acc[nt][2], acc[nt][3]);
        }
    }
}

// ---------------- fused attention: 2-edge pipelined segment softmax ----------------
__global__ __launch_bounds__(256) void attn_kernel(const float* __restrict__ x, int n) {
    int r = (blockIdx.x << 3) + (threadIdx.x >> 5);
    if (r >= n) return;
    int lane = threadIdx.x & 31;
    int j = lane & 7;

    const float4* qr = reinterpret_cast<const float4*>(g_Qp + (size_t)r * 256);
    float4 q0 = qr[lane * 2], q1 = qr[lane * 2 + 1];

    int beg = g_rowptr[r], end = g_rowptr[r + 1];
    float dsum = 0.f;
    float4 a0 = make_float4(0.f, 0.f, 0.f, 0.f);
    float4 a1 = a0;

    int p = beg;
    for (; p + 1 < end; p += 2) {
        int s0 = g_esend[p], s1 = g_esend[p + 1];
        const float4* xs0 = reinterpret_cast<const float4*>(x + (size_t)s0 * 64);
        const float4* xs1 = reinterpret_cast<const float4*>(x + (size_t)s1 * 64);
        float4 u0 = xs0[j * 2], u1 = xs0[j * 2 + 1];
        float4 w0 = xs1[j * 2], w1 = xs1[j * 2 + 1];

        float pa = q0.x * u0.x + q0.y * u0.y + q0.z * u0.z + q0.w * u0.w
                 + q1.x * u1.x + q1.y * u1.y + q1.z * u1.z + q1.w * u1.w;
        float pb = q0.x * w0.x + q0.y * w0.y + q0.z * w0.z + q0.w * w0.w
                 + q1.x * w1.x + q1.y * w1.y + q1.z * w1.z + q1.w * w1.w;
        pa += __shfl_xor_sync(0xffffffffu, pa, 1);
        pb += __shfl_xor_sync(0xffffffffu, pb, 1);
        pa += __shfl_xor_sync(0xffffffffu, pa, 2);
        pb += __shfl_xor_sync(0xffffffffu, pb, 2);
        pa += __shfl_xor_sync(0xffffffffu, pa, 4);
        pb += __shfl_xor_sync(0xffffffffu, pb, 4);

        float ea = __expf(pa);
        float eb = __expf(pb);
        dsum += ea + eb;
        a0.x += ea * u0.x + eb * w0.x; a0.y += ea * u0.y + eb * w0.y;
        a0.z += ea * u0.z + eb * w0.z; a0.w += ea * u0.w + eb * w0.w;
        a1.x += ea * u1.x + eb * w1.x; a1.y += ea * u1.y + eb * w1.y;
        a1.z += ea * u1.z + eb * w1.z; a1.w += ea * u1.w + eb * w1.w;
    }
    if (p < end) {
        int s = g_esend[p];
        const float4* xs = reinterpret_cast<const float4*>(x + (size_t)s * 64);
        float4 u0 = xs[j * 2], u1 = xs[j * 2 + 1];
        float pa = q0.x * u0.x + q0.y * u0.y + q0.z * u0.z + q0.w * u0.w
                 + q1.x * u1.x + q1.y * u1.y + q1.z * u1.z + q1.w * u1.w;
        pa += __shfl_xor_sync(0xffffffffu, pa, 1);
        pa += __shfl_xor_sync(0xffffffffu, pa, 2);
        pa += __shfl_xor_sync(0xffffffffu, pa, 4);
        float ea = __expf(pa);
        dsum += ea;
        a0.x += ea * u0.x; a0.y += ea * u0.y; a0.z += ea * u0.z; a0.w += ea * u0.w;
        a1.x += ea * u1.x; a1.y += ea * u1.y; a1.z += ea * u1.z; a1.w += ea * u1.w;
    }

    float rinv = (dsum > 0.f) ? (1.0f / dsum) : 0.f;
    a0.x *= rinv; a0.y *= rinv; a0.z *= rinv; a0.w *= rinv;
    a1.x *= rinv; a1.y *= rinv; a1.z *= rinv; a1.w *= rinv;

    float4* tr = reinterpret_cast<float4*>(g_T + (size_t)r * 256);
    tr[lane * 2] = a0;
    tr[lane * 2 + 1] = a1;
}

// ---------------- GEMM 2: out = x + T @ Wst  (tensor cores, 3xTF32) ----------------
// 256 threads / 8 warps; warp = ONE 16-row m-tile; k-chunks looped with sync.
__global__ __launch_bounds__(256) void gemm_out_kernel(const float* __restrict__ x,
                                                       float* __restrict__ out, int n) {
    __shared__ float As[128][68];
    int row0 = blockIdx.x * 128;
    int tid = threadIdx.x, warp = tid >> 5, lane = tid & 31;
    int rq = lane >> 2, rr = lane & 3;
    int rb = (warp << 4) + rq;

    float acc[8][4];
    #pragma unroll
    for (int nt = 0; nt < 8; nt++)
        #pragma unroll
        for (int q = 0; q < 4; q++) acc[nt][q] = 0.f;

    for (int kc = 0; kc < 4; kc++) {
        for (int i = tid; i < 2048; i += 256) {
            int r = i >> 4, k4 = (i & 15) << 2;
            int gr = row0 + r;
            float4 v = make_float4(0.f, 0.f, 0.f, 0.f);
            if (gr < n)
                v = *reinterpret_cast<const float4*>(g_T + (size_t)gr * 256 + kc * 64 + k4);
            *reinterpret_cast<float4*>(&As[r][k4]) = v;
        }
        __syncthreads();

        #pragma unroll
        for (int kt = 0; kt < 8; kt++) {
            int kb = (kt << 3) + rr;
            unsigned ah[4], al[4];
            f2tf32_split(As[rb][kb],         ah[0], al[0]);
            f2tf32_split(As[rb + 8][kb],     ah[1], al[1]);
            f2tf32_split(As[rb][kb + 4],     ah[2], al[2]);
            f2tf32_split(As[rb + 8][kb + 4], ah[3], al[3]);

            const uint4* Bf = g_WstF + ((kc * 8 + kt) * 8) * 32 + lane;
            #pragma unroll
            for (int nt = 0; nt < 8; nt++) {
                uint4 b = Bf[nt * 32];
                MMA_TF32(acc[nt], ah[0], ah[1], ah[2], ah[3], b.x, b.y);
                MMA_TF32(acc[nt], al[0], al[1], al[2], al[3], b.x, b.y);
                MMA_TF32(acc[nt], ah[0], ah[1], ah[2], ah[3], b.z, b.w);
            }
        }
        __syncthreads();
    }

    int r0 = row0 + rb;
    #pragma unroll
    for (int nt = 0; nt < 8; nt++) {
        int c = nt * 8 + rr * 2;
        if (r0 < n) {
            float2 xv = *reinterpret_cast<const float2*>(x + (size_t)r0 * 64 + c);
            *reinterpret_cast<float2*>(out + (size_t)r0 * 64 + c) =
                make_float2(acc[nt][0] + xv.x, acc[nt][1] + xv.y);
        }
        if (r0 + 8 < n) {
            float2 xv = *reinterpret_cast<const float2*>(x + (size_t)(r0 + 8) * 64 + c);
            *reinterpret_cast<float2*>(out + (size_t)(r0 + 8) * 64 + c) =
                make_float2(acc[nt][2] + xv.x, acc[nt][3] + xv.y);
        }
    }
}

// ---------------- launch ----------------
extern "C" void kernel_launch(void* const* d_in, const int* in_sizes, int n_in,
                              void* d_out, int out_size) {
    const float* x    = (const float*)d_in[0];
    const float* Wq   = (const float*)d_in[1];
    const float* Wk   = (const float*)d_in[2];
    const float* Wv   = (const float*)d_in[3];
    const float* Wout = (const float*)d_in[4];
    const int*   ei   = (const int*)d_in[5];

    int n = in_sizes[0] / FEAT;       // 50000
    int E = in_sizes[5] / 2;          // 400000
    const int* send = ei;
    const int* recv = ei + E;
    int nb = (n + 1023) / 1024;       // 49

    // Order keeps the profiler's fixed capture slot on gemm_qp.
    prep_mats_kernel<<<8, 256>>>(Wq, Wk, Wv, Wout);        // 1
    pack_frags_kernel<<<64, 256>>>();                      // 2
    zero_deg_kernel<<<(n + 511) / 512, 512>>>(n);          // 3
    gemm_qp_kernel<<<(n + 127) / 128, 256>>>(x, n);        // 4  <- profiled

    count_deg_kernel<<<(E + 511) / 512, 512>>>(recv, E);
    scan_blocks_kernel<<<nb, 1024>>>(n);
    scan_tops_kernel<<<1, 32>>>(nb, n);
    scan_add_kernel<<<nb, 1024>>>(n);
    scatter_edges_kernel<<<(E + 511) / 512, 512>>>(send, recv, E);

    attn_kernel<<<(n + 7) / 8, 256>>>(x, n);

    gemm_out_kernel<<<(n + 127) / 128, 256>>>(x, (float*)d_out, n);
}

// round 11
// speedup vs baseline: 1.0095x; 1.0095x over previous
#include <cuda_runtime.h>
#include <cstdint>

#define NNODES 50000
#define NEDGES 400000
#define FEAT   64
#define HEADS  4

// ---------------- scratch (static device globals; no allocation) ----------------
__device__ float g_Qp[(size_t)NNODES * 256];   // Q' = x @ M_h, layout [n][h*64+d]
__device__ float g_T [(size_t)NNODES * 256];   // segment-softmax-weighted sums of x_s
__device__ float g_M [HEADS * 64 * 64];        // M_h = Wq_h @ Wk_h^T * scale, [h][k][c]
__device__ float g_Wst[256 * 64];              // Wst[k][c] = (Wv@Wout)/4, k = h*64+f
__device__ uint4 g_BqpF[HEADS * 8 * 8 * 32];   // packed tf32 B frags for gemm_qp
__device__ uint4 g_WstF[32 * 8 * 32];          // packed tf32 B frags for gemm_out
__device__ int   g_deg   [NNODES];
__device__ int   g_rowptr[NNODES + 1];
__device__ int   g_cursor[NNODES];
__device__ int   g_esend [NEDGES];
__device__ int   g_bsum  [64];
__device__ int   g_bsumx [64];

// ---------------- tf32 helpers ----------------
__device__ __forceinline__ void f2tf32_split(float v, unsigned& hi, unsigned& lo) {
    asm("cvt.rna.tf32.f32 %0, %1;" : "=r"(hi) : "f"(v));
    float l = v - __uint_as_float(hi);
    asm("cvt.rna.tf32.f32 %0, %1;" : "=r"(lo) : "f"(l));
}

#define MMA_TF32(c, a0, a1, a2, a3, b0, b1)                                          \
    asm volatile(                                                                    \
        "mma.sync.aligned.m16n8k8.row.col.f32.tf32.tf32.f32 "                        \
        "{%0,%1,%2,%3}, {%4,%5,%6,%7}, {%8,%9}, {%0,%1,%2,%3};"                      \
        : "+f"((c)[0]), "+f"((c)[1]), "+f"((c)[2]), "+f"((c)[3])                     \
        : "r"(a0), "r"(a1), "r"(a2), "r"(a3), "r"(b0), "r"(b1))

// ---------------- small matrix prep ----------------
__global__ __launch_bounds__(256) void prep_mats_kernel(
    const float* __restrict__ Wq, const float* __restrict__ Wk,
    const float* __restrict__ Wv, const float* __restrict__ Wout)
{
    __shared__ float As[64 * 65];
    __shared__ float Bs[64 * 65];
    int b = blockIdx.x;
    int tid = threadIdx.x;

    if (b < 4) {
        int h = b;
        const float* A = Wq + h * 4096;
        const float* B = Wk + h * 4096;
        for (int i = tid; i < 4096; i += 256) {
            As[(i >> 6) * 65 + (i & 63)] = A[i];
            Bs[(i >> 6) * 65 + (i & 63)] = B[i];
        }
        __syncthreads();
        for (int o = tid; o < 4096; o += 256) {
            int f1 = o & 63, f2 = o >> 6;
            float s = 0.f;
            #pragma unroll 8
            for (int d = 0; d < 64; d++)
                s += As[f1 * 65 + d] * Bs[f2 * 65 + d];
            g_M[h * 4096 + f1 * 64 + f2] = s * 0.125f;
        }
    } else {
        int h = b - 4;
        const float* A = Wv + h * 4096;
        for (int i = tid; i < 4096; i += 256) {
            As[(i >> 6) * 65 + (i & 63)] = A[i];
            Bs[(i >> 6) * 65 + (i & 63)] = Wout[i];
        }
        __syncthreads();
        for (int o = tid; o < 4096; o += 256) {
            int f = o & 63, c = o >> 6;
            float s = 0.f;
            #pragma unroll 8
            for (int d = 0; d < 64; d++)
                s += As[f * 65 + d] * Bs[d * 65 + c];
            g_Wst[(h * 64 + f) * 64 + c] = s * 0.25f;
        }
    }
}

// pack B matrices into mma-fragment order with hi/lo tf32 split.
__global__ __launch_bounds__(256) void pack_frags_kernel() {
    int tid = blockIdx.x * 256 + threadIdx.x;
    if (tid < 8192) {
        int lane = tid & 31;
        int nt = (tid >> 5) & 7;
        int kt = (tid >> 8) & 7;
        int h  = tid >> 11;
        int k0 = kt * 8 + (lane & 3);
        int nn = nt * 8 + (lane >> 2);
        float v0 = g_M[h * 4096 + k0 * 64 + nn];
        float v1 = g_M[h * 4096 + (k0 + 4) * 64 + nn];
        uint4 o;
        f2tf32_split(v0, o.x, o.z);
        f2tf32_split(v1, o.y, o.w);
        g_BqpF[tid] = o;
    } else if (tid < 16384) {
        int t = tid - 8192;
        int lane = t & 31;
        int nt = (t >> 5) & 7;
        int kt = t >> 8;
        int k0 = kt * 8 + (lane & 3);
        int nn = nt * 8 + (lane >> 2);
        float v0 = g_Wst[k0 * 64 + nn];
        float v1 = g_Wst[(k0 + 4) * 64 + nn];
        uint4 o;
        f2tf32_split(v0, o.x, o.z);
        f2tf32_split(v1, o.y, o.w);
        g_WstF[t] = o;
    }
}

// ---------------- CSR build ----------------
__global__ void zero_deg_kernel(int n) {
    int i = blockIdx.x * blockDim.x + threadIdx.x;
    if (i < n) g_deg[i] = 0;
}

__global__ void count_deg_kernel(const int* __restrict__ recv, int E) {
    int i = blockIdx.x * blockDim.x + threadIdx.x;
    if (i < E) atomicAdd(&g_deg[recv[i]], 1);
}

__global__ __launch_bounds__(1024) void scan_blocks_kernel(int n) {
    __shared__ int wsum[32];
    int b = blockIdx.x;
    int tid = threadIdx.x, lane = tid & 31, wid = tid >> 5;
    int i = (b << 10) + tid;
    int v = (i < n) ? g_deg[i] : 0;
    int xi = v;
    #pragma unroll
    for (int o = 1; o < 32; o <<= 1) {
        int t = __shfl_up_sync(0xffffffffu, xi, o);
        if (lane >= o) xi += t;
    }
    if (lane == 31) wsum[wid] = xi;
    __syncthreads();
    if (wid == 0) {
        int s = wsum[lane];
        #pragma unroll
        for (int o = 1; o < 32; o <<= 1) {
            int t = __shfl_up_sync(0xffffffffu, s, o);
            if (lane >= o) s += t;
        }
        wsum[lane] = s;
    }
    __syncthreads();
    int incl = xi + (wid ? wsum[wid - 1] : 0);
    if (i < n) g_rowptr[i] = incl - v;
    if (tid == 1023) g_bsum[b] = incl;
}

__global__ __launch_bounds__(32) void scan_tops_kernel(int nb, int n) {
    int lane = threadIdx.x;
    int v0 = (lane < nb) ? g_bsum[lane] : 0;
    int v1 = (lane + 32 < nb) ? g_bsum[lane + 32] : 0;
    int s0 = v0;
    #pragma unroll
    for (int o = 1; o < 32; o <<= 1) {
        int t = __shfl_up_sync(0xffffffffu, s0, o);
        if (lane >= o) s0 += t;
    }
    int tot0 = __shfl_sync(0xffffffffu, s0, 31);
    int s1 = v1;
    #pragma unroll
    for (int o = 1; o < 32; o <<= 1) {
        int t = __shfl_up_sync(0xffffffffu, s1, o);
        if (lane >= o) s1 += t;
    }
    s1 += tot0;
    g_bsumx[lane] = s0 - v0;
    g_bsumx[lane + 32] = s1 - v1;
    if (lane == 31) g_rowptr[n] = s1;
}

__global__ __launch_bounds__(1024) void scan_add_kernel(int n) {
    int i = (blockIdx.x << 10) + threadIdx.x;
    if (i < n) {
        int r = g_rowptr[i] + g_bsumx[blockIdx.x];
        g_rowptr[i] = r;
        g_cursor[i] = r;
    }
}

__global__ void scatter_edges_kernel(const int* __restrict__ send,
                                     const int* __restrict__ recv, int E) {
    int i = blockIdx.x * blockDim.x + threadIdx.x;
    if (i < E) {
        int pos = atomicAdd(&g_cursor[recv[i]], 1);
        g_esend[pos] = send[i];
    }
}

// ---------------- GEMM 1: Q' = x @ M_h  (tensor cores, 3xTF32) ----------------
// 256 threads / 8 warps. Warp w: m-tile PAIR (w>>1) (rows (w>>1)*32..+31) and
// n-half (w&1) (4 n-tiles). Keeps round-9's 6-MMA-per-B-load amortization with
// round-10's 32-reg accumulators -> high occupancy AND low LSU pressure.
__global__ __launch_bounds__(256) void gemm_qp_kernel(const float* __restrict__ x, int n) {
    __shared__ float As[128][68];
    int row0 = blockIdx.x * 128;
    int tid = threadIdx.x, warp = tid >> 5, lane = tid & 31;
    int rq = lane >> 2, rr = lane & 3;
    int mtg = warp >> 1;                 // 0..3 -> rows mtg*32..+31
    int nh  = (warp & 1) << 2;           // n-tile base: 0 or 4
    int rb = (mtg << 5) + rq;            // rows rb, rb+8 (mt0); rb+16, rb+24 (mt1)

    for (int i = tid; i < 2048; i += 256) {
        int r = i >> 4, k4 = (i & 15) << 2;
        int gr = row0 + r;
        float4 v = make_float4(0.f, 0.f, 0.f, 0.f);
        if (gr < n) v = *reinterpret_cast<const float4*>(x + (size_t)gr * 64 + k4);
        *reinterpret_cast<float4*>(&As[r][k4]) = v;
    }
    __syncthreads();

    for (int h = 0; h < HEADS; h++) {
        float acc[2][4][4];
        #pragma unroll
        for (int mt = 0; mt < 2; mt++)
            #pragma unroll
            for (int nt = 0; nt < 4; nt++)
                #pragma unroll
                for (int q = 0; q < 4; q++) acc[mt][nt][q] = 0.f;

        #pragma unroll
        for (int kt = 0; kt < 8; kt++) {
            int kb = (kt << 3) + rr;
            unsigned ah[2][4], al[2][4];
            #pragma unroll
            for (int mt = 0; mt < 2; mt++) {
                int rm = rb + (mt << 4);
                f2tf32_split(As[rm][kb],         ah[mt][0], al[mt][0]);
                f2tf32_split(As[rm + 8][kb],     ah[mt][1], al[mt][1]);
                f2tf32_split(As[rm][kb + 4],     ah[mt][2], al[mt][2]);
                f2tf32_split(As[rm + 8][kb + 4], ah[mt][3], al[mt][3]);
            }
            const uint4* Bf = g_BqpF + ((h * 8 + kt) * 8 + nh) * 32 + lane;
            #pragma unroll
            for (int nt = 0; nt < 4; nt++) {
                uint4 b = Bf[nt * 32];
                #pragma unroll
                for (int mt = 0; mt < 2; mt++) {
                    MMA_TF32(acc[mt][nt], ah[mt][0], ah[mt][1], ah[mt][2], ah[mt][3], b.x, b.y);
                    MMA_TF32(acc[mt][nt], al[mt][0], al[mt][1], al[mt][2], al[mt][3], b.x, b.y);
                    MMA_TF32(acc[mt][nt], ah[mt][0], ah[mt][1], ah[mt][2], ah[mt][3], b.z, b.w);
                }
            }
        }

        #pragma unroll
        for (int mt = 0; mt < 2; mt++) {
            int r0 = row0 + rb + (mt << 4);
            #pragma unroll
            for (int nt = 0; nt < 4; nt++) {
                int c = h * 64 + (nh + nt) * 8 + rr * 2;
                if (r0 < n)
                    *reinterpret_cast<float2*>(g_Qp + (size_t)r0 * 256 + c) =
                        make_float2(acc[mt][nt][0], acc[mt][nt][1]);
                if (r0 + 8 < n)
                    *reinterpret_cast<float2*>(g_Qp + (size_t)(r0 + 8) * 256 + c) =
                        make_float2(acc[mt][nt][2], acc[mt][nt][3]);
            }
        }
    }
}

// ---------------- fused attention: 2-edge pipelined segment softmax ----------------
__global__ __launch_bounds__(256) void attn_kernel(const float* __restrict__ x, int n) {
    int r = (blockIdx.x << 3) + (threadIdx.x >> 5);
    if (r >= n) return;
    int lane = threadIdx.x & 31;
    int j = lane & 7;

    const float4* qr = reinterpret_cast<const float4*>(g_Qp + (size_t)r * 256);
    float4 q0 = qr[lane * 2], q1 = qr[lane * 2 + 1];

    int beg = g_rowptr[r], end = g_rowptr[r + 1];
    float dsum = 0.f;
    float4 a0 = make_float4(0.f, 0.f, 0.f, 0.f);
    float4 a1 = a0;

    int p = beg;
    for (; p + 1 < end; p += 2) {
        int s0 = g_esend[p], s1 = g_esend[p + 1];
        const float4* xs0 = reinterpret_cast<const float4*>(x + (size_t)s0 * 64);
        const float4* xs1 = reinterpret_cast<const float4*>(x + (size_t)s1 * 64);
        float4 u0 = xs0[j * 2], u1 = xs0[j * 2 + 1];
        float4 w0 = xs1[j * 2], w1 = xs1[j * 2 + 1];

        float pa = q0.x * u0.x + q0.y * u0.y + q0.z * u0.z + q0.w * u0.w
                 + q1.x * u1.x + q1.y * u1.y + q1.z * u1.z + q1.w * u1.w;
        float pb = q0.x * w0.x + q0.y * w0.y + q0.z * w0.z + q0.w * w0.w
                 + q1.x * w1.x + q1.y * w1.y + q1.z * w1.z + q1.w * w1.w;
        pa += __shfl_xor_sync(0xffffffffu, pa, 1);
        pb += __shfl_xor_sync(0xffffffffu, pb, 1);
        pa += __shfl_xor_sync(0xffffffffu, pa, 2);
        pb += __shfl_xor_sync(0xffffffffu, pb, 2);
        pa += __shfl_xor_sync(0xffffffffu, pa, 4);
        pb += __shfl_xor_sync(0xffffffffu, pb, 4);

        float ea = __expf(pa);
        float eb = __expf(pb);
        dsum += ea + eb;
        a0.x += ea * u0.x + eb * w0.x; a0.y += ea * u0.y + eb * w0.y;
        a0.z += ea * u0.z + eb * w0.z; a0.w += ea * u0.w + eb * w0.w;
        a1.x += ea * u1.x + eb * w1.x; a1.y += ea * u1.y + eb * w1.y;
        a1.z += ea * u1.z + eb * w1.z; a1.w += ea * u1.w + eb * w1.w;
    }
    if (p < end) {
        int s = g_esend[p];
        const float4* xs = reinterpret_cast<const float4*>(x + (size_t)s * 64);
        float4 u0 = xs[j * 2], u1 = xs[j * 2 + 1];
        float pa = q0.x * u0.x + q0.y * u0.y + q0.z * u0.z + q0.w * u0.w
                 + q1.x * u1.x + q1.y * u1.y + q1.z * u1.z + q1.w * u1.w;
        pa += __shfl_xor_sync(0xffffffffu, pa, 1);
        pa += __shfl_xor_sync(0xffffffffu, pa, 2);
        pa += __shfl_xor_sync(0xffffffffu, pa, 4);
        float ea = __expf(pa);
        dsum += ea;
        a0.x += ea * u0.x; a0.y += ea * u0.y; a0.z += ea * u0.z; a0.w += ea * u0.w;
        a1.x += ea * u1.x; a1.y += ea * u1.y; a1.z += ea * u1.z; a1.w += ea * u1.w;
    }

    float rinv = (dsum > 0.f) ? (1.0f / dsum) : 0.f;
    a0.x *= rinv; a0.y *= rinv; a0.z *= rinv; a0.w *= rinv;
    a1.x *= rinv; a1.y *= rinv; a1.z *= rinv; a1.w *= rinv;

    float4* tr = reinterpret_cast<float4*>(g_T + (size_t)r * 256);
    tr[lane * 2] = a0;
    tr[lane * 2 + 1] = a1;
}

// ---------------- GEMM 2: out = x + T @ Wst  (tensor cores, 3xTF32) ----------------
// same 2-m-tile x 4-n-tile warp shape as gemm_qp.
__global__ __launch_bounds__(256) void gemm_out_kernel(const float* __restrict__ x,
                                                       float* __restrict__ out, int n) {
    __shared__ float As[128][68];
    int row0 = blockIdx.x * 128;
    int tid = threadIdx.x, warp = tid >> 5, lane = tid & 31;
    int rq = lane >> 2, rr = lane & 3;
    int mtg = warp >> 1;
    int nh  = (warp & 1) << 2;
    int rb = (mtg << 5) + rq;

    float acc[2][4][4];
    #pragma unroll
    for (int mt = 0; mt < 2; mt++)
        #pragma unroll
        for (int nt = 0; nt < 4; nt++)
            #pragma unroll
            for (int q = 0; q < 4; q++) acc[mt][nt][q] = 0.f;

    for (int kc = 0; kc < 4; kc++) {
        for (int i = tid; i < 2048; i += 256) {
            int r = i >> 4, k4 = (i & 15) << 2;
            int gr = row0 + r;
            float4 v = make_float4(0.f, 0.f, 0.f, 0.f);
            if (gr < n)
                v = *reinterpret_cast<const float4*>(g_T + (size_t)gr * 256 + kc * 64 + k4);
            *reinterpret_cast<float4*>(&As[r][k4]) = v;
        }
        __syncthreads();

        #pragma unroll
        for (int kt = 0; kt < 8; kt++) {
            int kb = (kt << 3) + rr;
            unsigned ah[2][4], al[2][4];
            #pragma unroll
            for (int mt = 0; mt < 2; mt++) {
                int rm = rb + (mt << 4);
                f2tf32_split(As[rm][kb],         ah[mt][0], al[mt][0]);
                f2tf32_split(As[rm + 8][kb],     ah[mt][1], al[mt][1]);
                f2tf32_split(As[rm][kb + 4],     ah[mt][2], al[mt][2]);
                f2tf32_split(As[rm + 8][kb + 4], ah[mt][3], al[mt][3]);
            }
            const uint4* Bf = g_WstF + ((kc * 8 + kt) * 8 + nh) * 32 + lane;
            #pragma unroll
            for (int nt = 0; nt < 4; nt++) {
                uint4 b = Bf[nt * 32];
                #pragma unroll
                for (int mt = 0; mt < 2; mt++) {
                    MMA_TF32(acc[mt][nt], ah[mt][0], ah[mt][1], ah[mt][2], ah[mt][3], b.x, b.y);
                    MMA_TF32(acc[mt][nt], al[mt][0], al[mt][1], al[mt][2], al[mt][3], b.x, b.y);
                    MMA_TF32(acc[mt][nt], ah[mt][0], ah[mt][1], ah[mt][2], ah[mt][3], b.z, b.w);
                }
            }
        }
        __syncthreads();
    }

    #pragma unroll
    for (int mt = 0; mt < 2; mt++) {
        int r0 = row0 + rb + (mt << 4);
        #pragma unroll
        for (int nt = 0; nt < 4; nt++) {
            int c = (nh + nt) * 8 + rr * 2;
            if (r0 < n) {
                float2 xv = *reinterpret_cast<const float2*>(x + (size_t)r0 * 64 + c);
                *reinterpret_cast<float2*>(out + (size_t)r0 * 64 + c) =
                    make_float2(acc[mt][nt][0] + xv.x, acc[mt][nt][1] + xv.y);
            }
            if (r0 + 8 < n) {
                float2 xv = *reinterpret_cast<const float2*>(x + (size_t)(r0 + 8) * 64 + c);
                *reinterpret_cast<float2*>(out + (size_t)(r0 + 8) * 64 + c) =
                    make_float2(acc[mt][nt][2] + xv.x, acc[mt][nt][3] + xv.y);
            }
        }
    }
}

// ---------------- launch ----------------
extern "C" void kernel_launch(void* const* d_in, const int* in_sizes, int n_in,
                              void* d_out, int out_size) {
    const float* x    = (const float*)d_in[0];
    const float* Wq   = (const float*)d_in[1];
    const float* Wk   = (const float*)d_in[2];
    const float* Wv   = (const float*)d_in[3];
    const float* Wout = (const float*)d_in[4];
    const int*   ei   = (const int*)d_in[5];

    int n = in_sizes[0] / FEAT;       // 50000
    int E = in_sizes[5] / 2;          // 400000
    const int* send = ei;
    const int* recv = ei + E;
    int nb = (n + 1023) / 1024;       // 49

    // Order keeps the profiler's fixed capture slot on gemm_qp.
    prep_mats_kernel<<<8, 256>>>(Wq, Wk, Wv, Wout);        // 1
    pack_frags_kernel<<<64, 256>>>();                      // 2
    zero_deg_kernel<<<(n + 511) / 512, 512>>>(n);          // 3
    gemm_qp_kernel<<<(n + 127) / 128, 256>>>(x, n);        // 4  <- profiled

    count_deg_kernel<<<(E + 511) / 512, 512>>>(recv, E);
    scan_blocks_kernel<<<nb, 1024>>>(n);
    scan_tops_kernel<<<1, 32>>>(nb, n);
    scan_add_kernel<<<nb, 1024>>>(n);
    scatter_edges_kernel<<<(E + 511) / 512, 512>>>(send, recv, E);

    attn_kernel<<<(n + 7) / 8, 256>>>(x, n);

    gemm_out_kernel<<<(n + 127) / 128, 256>>>(x, (float*)d_out, n);
}

// round 12
// speedup vs baseline: 1.1434x; 1.1327x over previous
#include <cuda_runtime.h>
#include <cstdint>

#define NNODES 50000
#define NEDGES 400000
#define FEAT   64
#define HEADS  4

// ---------------- scratch (static device globals; no allocation) ----------------
__device__ float g_Qp[(size_t)NNODES * 256];   // Q' = x @ M_h, layout [n][h*64+d]
__device__ float g_T [(size_t)NNODES * 256];   // segment-softmax-weighted sums of x_s
__device__ float g_M [HEADS * 64 * 64];        // M_h = Wq_h @ Wk_h^T * scale, [h][k][c]
__device__ float g_Wst[256 * 64];              // Wst[k][c] = (Wv@Wout)/4, k = h*64+f
__device__ uint4 g_BqpF[HEADS * 8 * 8 * 32];   // packed tf32 B frags for gemm_qp
__device__ uint4 g_WstF[32 * 8 * 32];          // packed tf32 B frags for gemm_out
__device__ int   g_deg   [NNODES];
__device__ int   g_rowptr[NNODES + 1];
__device__ int   g_cursor[NNODES];
__device__ int   g_esend [NEDGES];
__device__ int   g_bsum  [64];
__device__ int   g_bsumx [64];

// ---------------- tf32 helpers ----------------
__device__ __forceinline__ void f2tf32_split(float v, unsigned& hi, unsigned& lo) {
    asm("cvt.rna.tf32.f32 %0, %1;" : "=r"(hi) : "f"(v));
    float l = v - __uint_as_float(hi);
    asm("cvt.rna.tf32.f32 %0, %1;" : "=r"(lo) : "f"(l));
}

#define MMA_TF32(c, a0, a1, a2, a3, b0, b1)                                          \
    asm volatile(                                                                    \
        "mma.sync.aligned.m16n8k8.row.col.f32.tf32.tf32.f32 "                        \
        "{%0,%1,%2,%3}, {%4,%5,%6,%7}, {%8,%9}, {%0,%1,%2,%3};"                      \
        : "+f"((c)[0]), "+f"((c)[1]), "+f"((c)[2]), "+f"((c)[3])                     \
        : "r"(a0), "r"(a1), "r"(a2), "r"(a3), "r"(b0), "r"(b1))

// ---------------- small matrix prep ----------------
__global__ __launch_bounds__(256) void prep_mats_kernel(
    const float* __restrict__ Wq, const float* __restrict__ Wk,
    const float* __restrict__ Wv, const float* __restrict__ Wout)
{
    __shared__ float As[64 * 65];
    __shared__ float Bs[64 * 65];
    int b = blockIdx.x;
    int tid = threadIdx.x;

    if (b < 4) {
        int h = b;
        const float* A = Wq + h * 4096;
        const float* B = Wk + h * 4096;
        for (int i = tid; i < 4096; i += 256) {
            As[(i >> 6) * 65 + (i & 63)] = A[i];
            Bs[(i >> 6) * 65 + (i & 63)] = B[i];
        }
        __syncthreads();
        for (int o = tid; o < 4096; o += 256) {
            int f1 = o & 63, f2 = o >> 6;
            float s = 0.f;
            #pragma unroll 8
            for (int d = 0; d < 64; d++)
                s += As[f1 * 65 + d] * Bs[f2 * 65 + d];
            g_M[h * 4096 + f1 * 64 + f2] = s * 0.125f;
        }
    } else {
        int h = b - 4;
        const float* A = Wv + h * 4096;
        for (int i = tid; i < 4096; i += 256) {
            As[(i >> 6) * 65 + (i & 63)] = A[i];
            Bs[(i >> 6) * 65 + (i & 63)] = Wout[i];
        }
        __syncthreads();
        for (int o = tid; o < 4096; o += 256) {
            int f = o & 63, c = o >> 6;
            float s = 0.f;
            #pragma unroll 8
            for (int d = 0; d < 64; d++)
                s += As[f * 65 + d] * Bs[d * 65 + c];
            g_Wst[(h * 64 + f) * 64 + c] = s * 0.25f;
        }
    }
}

// pack B matrices into mma-fragment order with hi/lo tf32 split.
__global__ __launch_bounds__(256) void pack_frags_kernel() {
    int tid = blockIdx.x * 256 + threadIdx.x;
    if (tid < 8192) {
        int lane = tid & 31;
        int nt = (tid >> 5) & 7;
        int kt = (tid >> 8) & 7;
        int h  = tid >> 11;
        int k0 = kt * 8 + (lane & 3);
        int nn = nt * 8 + (lane >> 2);
        float v0 = g_M[h * 4096 + k0 * 64 + nn];
        float v1 = g_M[h * 4096 + (k0 + 4) * 64 + nn];
        uint4 o;
        f2tf32_split(v0, o.x, o.z);
        f2tf32_split(v1, o.y, o.w);
        g_BqpF[tid] = o;
    } else if (tid < 16384) {
        int t = tid - 8192;
        int lane = t & 31;
        int nt = (t >> 5) & 7;
        int kt = t >> 8;
        int k0 = kt * 8 + (lane & 3);
        int nn = nt * 8 + (lane >> 2);
        float v0 = g_Wst[k0 * 64 + nn];
        float v1 = g_Wst[(k0 + 4) * 64 + nn];
        uint4 o;
        f2tf32_split(v0, o.x, o.z);
        f2tf32_split(v1, o.y, o.w);
        g_WstF[t] = o;
    }
}

// ---------------- CSR build ----------------
__global__ void zero_deg_kernel(int n) {
    int i = blockIdx.x * blockDim.x + threadIdx.x;
    if (i < n) g_deg[i] = 0;
}

__global__ void count_deg_kernel(const int* __restrict__ recv, int E) {
    int i = blockIdx.x * blockDim.x + threadIdx.x;
    if (i < E) atomicAdd(&g_deg[recv[i]], 1);
}

__global__ __launch_bounds__(1024) void scan_blocks_kernel(int n) {
    __shared__ int wsum[32];
    int b = blockIdx.x;
    int tid = threadIdx.x, lane = tid & 31, wid = tid >> 5;
    int i = (b << 10) + tid;
    int v = (i < n) ? g_deg[i] : 0;
    int xi = v;
    #pragma unroll
    for (int o = 1; o < 32; o <<= 1) {
        int t = __shfl_up_sync(0xffffffffu, xi, o);
        if (lane >= o) xi += t;
    }
    if (lane == 31) wsum[wid] = xi;
    __syncthreads();
    if (wid == 0) {
        int s = wsum[lane];
        #pragma unroll
        for (int o = 1; o < 32; o <<= 1) {
            int t = __shfl_up_sync(0xffffffffu, s, o);
            if (lane >= o) s += t;
        }
        wsum[lane] = s;
    }
    __syncthreads();
    int incl = xi + (wid ? wsum[wid - 1] : 0);
    if (i < n) g_rowptr[i] = incl - v;
    if (tid == 1023) g_bsum[b] = incl;
}

__global__ __launch_bounds__(32) void scan_tops_kernel(int nb, int n) {
    int lane = threadIdx.x;
    int v0 = (lane < nb) ? g_bsum[lane] : 0;
    int v1 = (lane + 32 < nb) ? g_bsum[lane + 32] : 0;
    int s0 = v0;
    #pragma unroll
    for (int o = 1; o < 32; o <<= 1) {
        int t = __shfl_up_sync(0xffffffffu, s0, o);
        if (lane >= o) s0 += t;
    }
    int tot0 = __shfl_sync(0xffffffffu, s0, 31);
    int s1 = v1;
    #pragma unroll
    for (int o = 1; o < 32; o <<= 1) {
        int t = __shfl_up_sync(0xffffffffu, s1, o);
        if (lane >= o) s1 += t;
    }
    s1 += tot0;
    g_bsumx[lane] = s0 - v0;
    g_bsumx[lane + 32] = s1 - v1;
    if (lane == 31) g_rowptr[n] = s1;
}

__global__ __launch_bounds__(1024) void scan_add_kernel(int n) {
    int i = (blockIdx.x << 10) + threadIdx.x;
    if (i < n) {
        int r = g_rowptr[i] + g_bsumx[blockIdx.x];
        g_rowptr[i] = r;
        g_cursor[i] = r;
    }
}

__global__ void scatter_edges_kernel(const int* __restrict__ send,
                                     const int* __restrict__ recv, int E) {
    int i = blockIdx.x * blockDim.x + threadIdx.x;
    if (i < E) {
        int pos = atomicAdd(&g_cursor[recv[i]], 1);
        g_esend[pos] = send[i];
    }
}

// ---------------- GEMM 1: Q' = x @ M_h  (tensor cores, 3xTF32) ----------------
// R9 shape (128 threads, warp = 2 m-tiles x 8 n-tiles) with pass-reordered MMAs:
// each accumulator re-touched only after 8 independent MMAs -> no RAW stalls.
__global__ __launch_bounds__(128) void gemm_qp_kernel(const float* __restrict__ x, int n) {
    __shared__ float As[128][68];
    int row0 = blockIdx.x * 128;
    int tid = threadIdx.x, warp = tid >> 5, lane = tid & 31;
    int rq = lane >> 2, rr = lane & 3;

    for (int i = tid; i < 2048; i += 128) {
        int r = i >> 4, k4 = (i & 15) << 2;
        int gr = row0 + r;
        float4 v = make_float4(0.f, 0.f, 0.f, 0.f);
        if (gr < n) v = *reinterpret_cast<const float4*>(x + (size_t)gr * 64 + k4);
        *reinterpret_cast<float4*>(&As[r][k4]) = v;
    }
    __syncthreads();

    for (int h = 0; h < HEADS; h++) {
        float acc[2][8][4];
        #pragma unroll
        for (int mt = 0; mt < 2; mt++)
            #pragma unroll
            for (int nt = 0; nt < 8; nt++)
                #pragma unroll
                for (int q = 0; q < 4; q++) acc[mt][nt][q] = 0.f;

        #pragma unroll
        for (int kt = 0; kt < 8; kt++) {
            unsigned ah[2][4], al[2][4];
            #pragma unroll
            for (int mt = 0; mt < 2; mt++) {
                int rb = (warp << 5) + (mt << 4) + rq;
                int kb = (kt << 3) + rr;
                f2tf32_split(As[rb][kb],         ah[mt][0], al[mt][0]);
                f2tf32_split(As[rb + 8][kb],     ah[mt][1], al[mt][1]);
                f2tf32_split(As[rb][kb + 4],     ah[mt][2], al[mt][2]);
                f2tf32_split(As[rb + 8][kb + 4], ah[mt][3], al[mt][3]);
            }
            const uint4* Bf = g_BqpF + ((h * 8 + kt) * 8) * 32 + lane;
            #pragma unroll
            for (int half = 0; half < 2; half++) {
                uint4 b[4];
                #pragma unroll
                for (int nt = 0; nt < 4; nt++) b[nt] = Bf[(half * 4 + nt) * 32];
                // pass 1: hi * B_hi  (8 independent MMAs)
                #pragma unroll
                for (int nt = 0; nt < 4; nt++)
                    #pragma unroll
                    for (int mt = 0; mt < 2; mt++)
                        MMA_TF32(acc[mt][half * 4 + nt],
                                 ah[mt][0], ah[mt][1], ah[mt][2], ah[mt][3],
                                 b[nt].x, b[nt].y);
                // pass 2: lo * B_hi
                #pragma unroll
                for (int nt = 0; nt < 4; nt++)
                    #pragma unroll
                    for (int mt = 0; mt < 2; mt++)
                        MMA_TF32(acc[mt][half * 4 + nt],
                                 al[mt][0], al[mt][1], al[mt][2], al[mt][3],
                                 b[nt].x, b[nt].y);
                // pass 3: hi * B_lo
                #pragma unroll
                for (int nt = 0; nt < 4; nt++)
                    #pragma unroll
                    for (int mt = 0; mt < 2; mt++)
                        MMA_TF32(acc[mt][half * 4 + nt],
                                 ah[mt][0], ah[mt][1], ah[mt][2], ah[mt][3],
                                 b[nt].z, b[nt].w);
            }
        }

        #pragma unroll
        for (int mt = 0; mt < 2; mt++) {
            int r0 = row0 + (warp << 5) + (mt << 4) + rq;
            #pragma unroll
            for (int nt = 0; nt < 8; nt++) {
                int c = h * 64 + nt * 8 + rr * 2;
                if (r0 < n)
                    *reinterpret_cast<float2*>(g_Qp + (size_t)r0 * 256 + c) =
                        make_float2(acc[mt][nt][0], acc[mt][nt][1]);
                if (r0 + 8 < n)
                    *reinterpret_cast<float2*>(g_Qp + (size_t)(r0 + 8) * 256 + c) =
                        make_float2(acc[mt][nt][2], acc[mt][nt][3]);
            }
        }
    }
}

// ---------------- fused attention: 2-edge pipelined segment softmax ----------------
__global__ __launch_bounds__(256) void attn_kernel(const float* __restrict__ x, int n) {
    int r = (blockIdx.x << 3) + (threadIdx.x >> 5);
    if (r >= n) return;
    int lane = threadIdx.x & 31;
    int j = lane & 7;

    const float4* qr = reinterpret_cast<const float4*>(g_Qp + (size_t)r * 256);
    float4 q0 = qr[lane * 2], q1 = qr[lane * 2 + 1];

    int beg = g_rowptr[r], end = g_rowptr[r + 1];
    float dsum = 0.f;
    float4 a0 = make_float4(0.f, 0.f, 0.f, 0.f);
    float4 a1 = a0;

    int p = beg;
    for (; p + 1 < end; p += 2) {
        int s0 = g_esend[p], s1 = g_esend[p + 1];
        const float4* xs0 = reinterpret_cast<const float4*>(x + (size_t)s0 * 64);
        const float4* xs1 = reinterpret_cast<const float4*>(x + (size_t)s1 * 64);
        float4 u0 = xs0[j * 2], u1 = xs0[j * 2 + 1];
        float4 w0 = xs1[j * 2], w1 = xs1[j * 2 + 1];

        float pa = q0.x * u0.x + q0.y * u0.y + q0.z * u0.z + q0.w * u0.w
                 + q1.x * u1.x + q1.y * u1.y + q1.z * u1.z + q1.w * u1.w;
        float pb = q0.x * w0.x + q0.y * w0.y + q0.z * w0.z + q0.w * w0.w
                 + q1.x * w1.x + q1.y * w1.y + q1.z * w1.z + q1.w * w1.w;
        pa += __shfl_xor_sync(0xffffffffu, pa, 1);
        pb += __shfl_xor_sync(0xffffffffu, pb, 1);
        pa += __shfl_xor_sync(0xffffffffu, pa, 2);
        pb += __shfl_xor_sync(0xffffffffu, pb, 2);
        pa += __shfl_xor_sync(0xffffffffu, pa, 4);
        pb += __shfl_xor_sync(0xffffffffu, pb, 4);

        float ea = __expf(pa);
        float eb = __expf(pb);
        dsum += ea + eb;
        a0.x += ea * u0.x + eb * w0.x; a0.y += ea * u0.y + eb * w0.y;
        a0.z += ea * u0.z + eb * w0.z; a0.w += ea * u0.w + eb * w0.w;
        a1.x += ea * u1.x + eb * w1.x; a1.y += ea * u1.y + eb * w1.y;
        a1.z += ea * u1.z + eb * w1.z; a1.w += ea * u1.w + eb * w1.w;
    }
    if (p < end) {
        int s = g_esend[p];
        const float4* xs = reinterpret_cast<const float4*>(x + (size_t)s * 64);
        float4 u0 = xs[j * 2], u1 = xs[j * 2 + 1];
        float pa = q0.x * u0.x + q0.y * u0.y + q0.z * u0.z + q0.w * u0.w
                 + q1.x * u1.x + q1.y * u1.y + q1.z * u1.z + q1.w * u1.w;
        pa += __shfl_xor_sync(0xffffffffu, pa, 1);
        pa += __shfl_xor_sync(0xffffffffu, pa, 2);
        pa += __shfl_xor_sync(0xffffffffu, pa, 4);
        float ea = __expf(pa);
        dsum += ea;
        a0.x += ea * u0.x; a0.y += ea * u0.y; a0.z += ea * u0.z; a0.w += ea * u0.w;
        a1.x += ea * u1.x; a1.y += ea * u1.y; a1.z += ea * u1.z; a1.w += ea * u1.w;
    }

    float rinv = (dsum > 0.f) ? (1.0f / dsum) : 0.f;
    a0.x *= rinv; a0.y *= rinv; a0.z *= rinv; a0.w *= rinv;
    a1.x *= rinv; a1.y *= rinv; a1.z *= rinv; a1.w *= rinv;

    float4* tr = reinterpret_cast<float4*>(g_T + (size_t)r * 256);
    tr[lane * 2] = a0;
    tr[lane * 2 + 1] = a1;
}

// ---------------- GEMM 2: out = x + T @ Wst  (tensor cores, 3xTF32) ----------------
// R9 shape with the same pass-reordered MMA issue.
__global__ __launch_bounds__(128) void gemm_out_kernel(const float* __restrict__ x,
                                                       float* __restrict__ out, int n) {
    __shared__ float As[128][68];
    int row0 = blockIdx.x * 128;
    int tid = threadIdx.x, warp = tid >> 5, lane = tid & 31;
    int rq = lane >> 2, rr = lane & 3;

    float acc[2][8][4];
    #pragma unroll
    for (int mt = 0; mt < 2; mt++)
        #pragma unroll
        for (int nt = 0; nt < 8; nt++)
            #pragma unroll
            for (int q = 0; q < 4; q++) acc[mt][nt][q] = 0.f;

    for (int kc = 0; kc < 4; kc++) {
        for (int i = tid; i < 2048; i += 128) {
            int r = i >> 4, k4 = (i & 15) << 2;
            int gr = row0 + r;
            float4 v = make_float4(0.f, 0.f, 0.f, 0.f);
            if (gr < n)
                v = *reinterpret_cast<const float4*>(g_T + (size_t)gr * 256 + kc * 64 + k4);
            *reinterpret_cast<float4*>(&As[r][k4]) = v;
        }
        __syncthreads();

        #pragma unroll
        for (int kt = 0; kt < 8; kt++) {
            unsigned ah[2][4], al[2][4];
            #pragma unroll
            for (int mt = 0; mt < 2; mt++) {
                int rb = (warp << 5) + (mt << 4) + rq;
                int kb = (kt << 3) + rr;
                f2tf32_split(As[rb][kb],         ah[mt][0], al[mt][0]);
                f2tf32_split(As[rb + 8][kb],     ah[mt][1], al[mt][1]);
                f2tf32_split(As[rb][kb + 4],     ah[mt][2], al[mt][2]);
                f2tf32_split(As[rb + 8][kb + 4], ah[mt][3], al[mt][3]);
            }
            const uint4* Bf = g_WstF + ((kc * 8 + kt) * 8) * 32 + lane;
            #pragma unroll
            for (int half = 0; half < 2; half++) {
                uint4 b[4];
                #pragma unroll
                for (int nt = 0; nt < 4; nt++) b[nt] = Bf[(half * 4 + nt) * 32];
                #pragma unroll
                for (int nt = 0; nt < 4; nt++)
                    #pragma unroll
                    for (int mt = 0; mt < 2; mt++)
                        MMA_TF32(acc[mt][half * 4 + nt],
                                 ah[mt][0], ah[mt][1], ah[mt][2], ah[mt][3],
                                 b[nt].x, b[nt].y);
                #pragma unroll
                for (int nt = 0; nt < 4; nt++)
                    #pragma unroll
                    for (int mt = 0; mt < 2; mt++)
                        MMA_TF32(acc[mt][half * 4 + nt],
                                 al[mt][0], al[mt][1], al[mt][2], al[mt][3],
                                 b[nt].x, b[nt].y);
                #pragma unroll
                for (int nt = 0; nt < 4; nt++)
                    #pragma unroll
                    for (int mt = 0; mt < 2; mt++)
                        MMA_TF32(acc[mt][half * 4 + nt],
                                 ah[mt][0], ah[mt][1], ah[mt][2], ah[mt][3],
                                 b[nt].z, b[nt].w);
            }
        }
        __syncthreads();
    }

    #pragma unroll
    for (int mt = 0; mt < 2; mt++) {
        int r0 = row0 + (warp << 5) + (mt << 4) + rq;
        #pragma unroll
        for (int nt = 0; nt < 8; nt++) {
            int c = nt * 8 + rr * 2;
            if (r0 < n) {
                float2 xv = *reinterpret_cast<const float2*>(x + (size_t)r0 * 64 + c);
                *reinterpret_cast<float2*>(out + (size_t)r0 * 64 + c) =
                    make_float2(acc[mt][nt][0] + xv.x, acc[mt][nt][1] + xv.y);
            }
            if (r0 + 8 < n) {
                float2 xv = *reinterpret_cast<const float2*>(x + (size_t)(r0 + 8) * 64 + c);
                *reinterpret_cast<float2*>(out + (size_t)(r0 + 8) * 64 + c) =
                    make_float2(acc[mt][nt][2] + xv.x, acc[mt][nt][3] + xv.y);
            }
        }
    }
}

// ---------------- launch ----------------
extern "C" void kernel_launch(void* const* d_in, const int* in_sizes, int n_in,
                              void* d_out, int out_size) {
    const float* x    = (const float*)d_in[0];
    const float* Wq   = (const float*)d_in[1];
    const float* Wk   = (const float*)d_in[2];
    const float* Wv   = (const float*)d_in[3];
    const float* Wout = (const float*)d_in[4];
    const int*   ei   = (const int*)d_in[5];

    int n = in_sizes[0] / FEAT;       // 50000
    int E = in_sizes[5] / 2;          // 400000
    const int* send = ei;
    const int* recv = ei + E;
    int nb = (n + 1023) / 1024;       // 49

    // Order keeps the profiler's fixed capture slot on gemm_qp.
    prep_mats_kernel<<<8, 256>>>(Wq, Wk, Wv, Wout);        // 1
    pack_frags_kernel<<<64, 256>>>();                      // 2
    zero_deg_kernel<<<(n + 511) / 512, 512>>>(n);          // 3
    gemm_qp_kernel<<<(n + 127) / 128, 128>>>(x, n);        // 4  <- profiled

    count_deg_kernel<<<(E + 511) / 512, 512>>>(recv, E);
    scan_blocks_kernel<<<nb, 1024>>>(n);
    scan_tops_kernel<<<1, 32>>>(nb, n);
    scan_add_kernel<<<nb, 1024>>>(n);
    scatter_edges_kernel<<<(E + 511) / 512, 512>>>(send, recv, E);

    attn_kernel<<<(n + 7) / 8, 256>>>(x, n);

    gemm_out_kernel<<<(n + 127) / 128, 128>>>(x, (float*)d_out, n);
}

// round 13
// speedup vs baseline: 1.3138x; 1.1490x over previous
#include <cuda_runtime.h>
#include <cuda_bf16.h>
#include <cstdint>

#define NNODES 50000
#define NEDGES 400000
#define FEAT   64
#define HEADS  4

// ---------------- scratch (static device globals; no allocation) ----------------
__device__ float g_Qp[(size_t)NNODES * 256];   // Q' = x @ M_h, layout [n][h*64+d]
__device__ float g_T [(size_t)NNODES * 256];   // segment-softmax-weighted sums of x_s
__device__ float g_M [HEADS * 64 * 64];        // M_h = Wq_h @ Wk_h^T * scale, [h][k][c]
__device__ float g_Wst[256 * 64];              // Wst[k][c] = (Wv@Wout)/4, k = h*64+f
__device__ uint4 g_BqpF[HEADS * 4 * 8 * 32];   // packed bf16 B frags {bh0,bh1,bl0,bl1}, k16 tiles
__device__ uint4 g_WstF[16 * 8 * 32];          // packed bf16 B frags for gemm_out
__device__ int   g_deg   [NNODES];
__device__ int   g_rowptr[NNODES + 1];
__device__ int   g_cursor[NNODES];
__device__ int   g_esend [NEDGES];
__device__ int   g_bsum  [64];
__device__ int   g_bsumx [64];

// ---------------- bf16 split helpers ----------------
__device__ __forceinline__ float bf_hi(float a) {
    return __bfloat162float(__float2bfloat16(a));
}
// pack two floats to bf16x2: lo -> bits[0:16), hi -> bits[16:32)
__device__ __forceinline__ unsigned pack_bf16(float lo, float hi) {
    unsigned d;
    asm("cvt.rn.bf16x2.f32 %0, %1, %2;" : "=r"(d) : "f"(hi), "f"(lo));
    return d;
}

#define MMA_BF16(c, a0, a1, a2, a3, b0, b1)                                          \
    asm volatile(                                                                    \
        "mma.sync.aligned.m16n8k16.row.col.f32.bf16.bf16.f32 "                       \
        "{%0,%1,%2,%3}, {%4,%5,%6,%7}, {%8,%9}, {%0,%1,%2,%3};"                      \
        : "+f"((c)[0]), "+f"((c)[1]), "+f"((c)[2]), "+f"((c)[3])                     \
        : "r"(a0), "r"(a1), "r"(a2), "r"(a3), "r"(b0), "r"(b1))

// ---------------- small matrix prep ----------------
__global__ __launch_bounds__(256) void prep_mats_kernel(
    const float* __restrict__ Wq, const float* __restrict__ Wk,
    const float* __restrict__ Wv, const float* __restrict__ Wout)
{
    __shared__ float As[64 * 65];
    __shared__ float Bs[64 * 65];
    int b = blockIdx.x;
    int tid = threadIdx.x;

    if (b < 4) {
        int h = b;
        const float* A = Wq + h * 4096;
        const float* B = Wk + h * 4096;
        for (int i = tid; i < 4096; i += 256) {
            As[(i >> 6) * 65 + (i & 63)] = A[i];
            Bs[(i >> 6) * 65 + (i & 63)] = B[i];
        }
        __syncthreads();
        for (int o = tid; o < 4096; o += 256) {
            int f1 = o & 63, f2 = o >> 6;
            float s = 0.f;
            #pragma unroll 8
            for (int d = 0; d < 64; d++)
                s += As[f1 * 65 + d] * Bs[f2 * 65 + d];
            g_M[h * 4096 + f1 * 64 + f2] = s * 0.125f;
        }
    } else {
        int h = b - 4;
        const float* A = Wv + h * 4096;
        for (int i = tid; i < 4096; i += 256) {
            As[(i >> 6) * 65 + (i & 63)] = A[i];
            Bs[(i >> 6) * 65 + (i & 63)] = Wout[i];
        }
        __syncthreads();
        for (int o = tid; o < 4096; o += 256) {
            int f = o & 63, c = o >> 6;
            float s = 0.f;
            #pragma unroll 8
            for (int d = 0; d < 64; d++)
                s += As[f * 65 + d] * Bs[d * 65 + c];
            g_Wst[(h * 64 + f) * 64 + c] = s * 0.25f;
        }
    }
}

// pack B matrices into m16n8k16 fragment order with bf16 hi/lo split.
// B frag (col-major k16 x n8): lane(rq=lane>>2, rr=lane&3):
//   reg0 = {B[k0][n], B[k0+1][n]},  reg1 = {B[k0+8][n], B[k0+9][n]},  k0 = kt*16 + rr*2, n = nt*8 + rq
__global__ __launch_bounds__(256) void pack_frags_kernel() {
    int tid = blockIdx.x * 256 + threadIdx.x;
    if (tid < 4096) {
        int lane = tid & 31;
        int nt = (tid >> 5) & 7;
        int kt = (tid >> 8) & 3;
        int h  = tid >> 10;
        int rr = lane & 3, rq = lane >> 2;
        int n  = nt * 8 + rq;
        int k0 = kt * 16 + rr * 2;
        const float* B = g_M + h * 4096;
        float v00 = B[k0 * 64 + n],       v01 = B[(k0 + 1) * 64 + n];
        float v10 = B[(k0 + 8) * 64 + n], v11 = B[(k0 + 9) * 64 + n];
        float h00 = bf_hi(v00), h01 = bf_hi(v01), h10 = bf_hi(v10), h11 = bf_hi(v11);
        uint4 o;
        o.x = pack_bf16(h00, h01);
        o.y = pack_bf16(h10, h11);
        o.z = pack_bf16(v00 - h00, v01 - h01);
        o.w = pack_bf16(v10 - h10, v11 - h11);
        g_BqpF[tid] = o;
    } else if (tid < 8192) {
        int t = tid - 4096;
        int lane = t & 31;
        int nt = (t >> 5) & 7;
        int kt = t >> 8;                 // 0..15
        int rr = lane & 3, rq = lane >> 2;
        int n  = nt * 8 + rq;
        int k0 = kt * 16 + rr * 2;
        float v00 = g_Wst[k0 * 64 + n],       v01 = g_Wst[(k0 + 1) * 64 + n];
        float v10 = g_Wst[(k0 + 8) * 64 + n], v11 = g_Wst[(k0 + 9) * 64 + n];
        float h00 = bf_hi(v00), h01 = bf_hi(v01), h10 = bf_hi(v10), h11 = bf_hi(v11);
        uint4 o;
        o.x = pack_bf16(h00, h01);
        o.y = pack_bf16(h10, h11);
        o.z = pack_bf16(v00 - h00, v01 - h01);
        o.w = pack_bf16(v10 - h10, v11 - h11);
        g_WstF[t] = o;
    }
}

// ---------------- CSR build ----------------
__global__ void zero_deg_kernel(int n) {
    int i = blockIdx.x * blockDim.x + threadIdx.x;
    if (i < n) g_deg[i] = 0;
}

__global__ void count_deg_kernel(const int* __restrict__ recv, int E) {
    int i = blockIdx.x * blockDim.x + threadIdx.x;
    if (i < E) atomicAdd(&g_deg[recv[i]], 1);
}

__global__ __launch_bounds__(1024) void scan_blocks_kernel(int n) {
    __shared__ int wsum[32];
    int b = blockIdx.x;
    int tid = threadIdx.x, lane = tid & 31, wid = tid >> 5;
    int i = (b << 10) + tid;
    int v = (i < n) ? g_deg[i] : 0;
    int xi = v;
    #pragma unroll
    for (int o = 1; o < 32; o <<= 1) {
        int t = __shfl_up_sync(0xffffffffu, xi, o);
        if (lane >= o) xi += t;
    }
    if (lane == 31) wsum[wid] = xi;
    __syncthreads();
    if (wid == 0) {
        int s = wsum[lane];
        #pragma unroll
        for (int o = 1; o < 32; o <<= 1) {
            int t = __shfl_up_sync(0xffffffffu, s, o);
            if (lane >= o) s += t;
        }
        wsum[lane] = s;
    }
    __syncthreads();
    int incl = xi + (wid ? wsum[wid - 1] : 0);
    if (i < n) g_rowptr[i] = incl - v;
    if (tid == 1023) g_bsum[b] = incl;
}

__global__ __launch_bounds__(32) void scan_tops_kernel(int nb, int n) {
    int lane = threadIdx.x;
    int v0 = (lane < nb) ? g_bsum[lane] : 0;
    int v1 = (lane + 32 < nb) ? g_bsum[lane + 32] : 0;
    int s0 = v0;
    #pragma unroll
    for (int o = 1; o < 32; o <<= 1) {
        int t = __shfl_up_sync(0xffffffffu, s0, o);
        if (lane >= o) s0 += t;
    }
    int tot0 = __shfl_sync(0xffffffffu, s0, 31);
    int s1 = v1;
    #pragma unroll
    for (int o = 1; o < 32; o <<= 1) {
        int t = __shfl_up_sync(0xffffffffu, s1, o);
        if (lane >= o) s1 += t;
    }
    s1 += tot0;
    g_bsumx[lane] = s0 - v0;
    g_bsumx[lane + 32] = s1 - v1;
    if (lane == 31) g_rowptr[n] = s1;
}

__global__ __launch_bounds__(1024) void scan_add_kernel(int n) {
    int i = (blockIdx.x << 10) + threadIdx.x;
    if (i < n) {
        int r = g_rowptr[i] + g_bsumx[blockIdx.x];
        g_rowptr[i] = r;
        g_cursor[i] = r;
    }
}

__global__ void scatter_edges_kernel(const int* __restrict__ send,
                                     const int* __restrict__ recv, int E) {
    int i = blockIdx.x * blockDim.x + threadIdx.x;
    if (i < E) {
        int pos = atomicAdd(&g_cursor[recv[i]], 1);
        g_esend[pos] = send[i];
    }
}

// A-fragment build: rows {rb, rb+8}, k pairs {kb, kb+1} and {kb+8, kb+9}
__device__ __forceinline__ void build_a_frags(
    const float (*As)[68], int rb, int kb, unsigned* ah, unsigned* al)
{
    float2 x0 = *reinterpret_cast<const float2*>(&As[rb][kb]);
    float2 x1 = *reinterpret_cast<const float2*>(&As[rb + 8][kb]);
    float2 x2 = *reinterpret_cast<const float2*>(&As[rb][kb + 8]);
    float2 x3 = *reinterpret_cast<const float2*>(&As[rb + 8][kb + 8]);
    float h0x = bf_hi(x0.x), h0y = bf_hi(x0.y);
    float h1x = bf_hi(x1.x), h1y = bf_hi(x1.y);
    float h2x = bf_hi(x2.x), h2y = bf_hi(x2.y);
    float h3x = bf_hi(x3.x), h3y = bf_hi(x3.y);
    ah[0] = pack_bf16(h0x, h0y);
    ah[1] = pack_bf16(h1x, h1y);
    ah[2] = pack_bf16(h2x, h2y);
    ah[3] = pack_bf16(h3x, h3y);
    al[0] = pack_bf16(x0.x - h0x, x0.y - h0y);
    al[1] = pack_bf16(x1.x - h1x, x1.y - h1y);
    al[2] = pack_bf16(x2.x - h2x, x2.y - h2y);
    al[3] = pack_bf16(x3.x - h3x, x3.y - h3y);
}

// ---------------- GEMM 1: Q' = x @ M_h  (tensor cores, 3-term BF16, m16n8k16) ----------------
// R9 shape: 128 threads / 4 warps, warp = 2 m-tiles x 8 n-tiles; K=16 per step.
__global__ __launch_bounds__(128) void gemm_qp_kernel(const float* __restrict__ x, int n) {
    __shared__ float As[128][68];
    int row0 = blockIdx.x * 128;
    int tid = threadIdx.x, warp = tid >> 5, lane = tid & 31;
    int rq = lane >> 2, rr = lane & 3;

    for (int i = tid; i < 2048; i += 128) {
        int r = i >> 4, k4 = (i & 15) << 2;
        int gr = row0 + r;
        float4 v = make_float4(0.f, 0.f, 0.f, 0.f);
        if (gr < n) v = *reinterpret_cast<const float4*>(x + (size_t)gr * 64 + k4);
        *reinterpret_cast<float4*>(&As[r][k4]) = v;
    }
    __syncthreads();

    for (int h = 0; h < HEADS; h++) {
        float acc[2][8][4];
        #pragma unroll
        for (int mt = 0; mt < 2; mt++)
            #pragma unroll
            for (int nt = 0; nt < 8; nt++)
                #pragma unroll
                for (int q = 0; q < 4; q++) acc[mt][nt][q] = 0.f;

        #pragma unroll
        for (int kt = 0; kt < 4; kt++) {          // K=16 per step
            int kb = (kt << 4) + rr * 2;
            unsigned ah[2][4], al[2][4];
            #pragma unroll
            for (int mt = 0; mt < 2; mt++)
                build_a_frags(As, (warp << 5) + (mt << 4) + rq, kb, ah[mt], al[mt]);

            const uint4* Bf = g_BqpF + ((h * 4 + kt) * 8) * 32 + lane;
            #pragma unroll
            for (int half = 0; half < 2; half++) {
                uint4 b[4];
                #pragma unroll
                for (int nt = 0; nt < 4; nt++) b[nt] = Bf[(half * 4 + nt) * 32];
                // pass 1: A_hi * B_hi
                #pragma unroll
                for (int nt = 0; nt < 4; nt++)
                    #pragma unroll
                    for (int mt = 0; mt < 2; mt++)
                        MMA_BF16(acc[mt][half * 4 + nt],
                                 ah[mt][0], ah[mt][1], ah[mt][2], ah[mt][3],
                                 b[nt].x, b[nt].y);
                // pass 2: A_lo * B_hi
                #pragma unroll
                for (int nt = 0; nt < 4; nt++)
                    #pragma unroll
                    for (int mt = 0; mt < 2; mt++)
                        MMA_BF16(acc[mt][half * 4 + nt],
                                 al[mt][0], al[mt][1], al[mt][2], al[mt][3],
                                 b[nt].x, b[nt].y);
                // pass 3: A_hi * B_lo
                #pragma unroll
                for (int nt = 0; nt < 4; nt++)
                    #pragma unroll
                    for (int mt = 0; mt < 2; mt++)
                        MMA_BF16(acc[mt][half * 4 + nt],
                                 ah[mt][0], ah[mt][1], ah[mt][2], ah[mt][3],
                                 b[nt].z, b[nt].w);
            }
        }

        #pragma unroll
        for (int mt = 0; mt < 2; mt++) {
            int r0 = row0 + (warp << 5) + (mt << 4) + rq;
            #pragma unroll
            for (int nt = 0; nt < 8; nt++) {
                int c = h * 64 + nt * 8 + rr * 2;
                if (r0 < n)
                    *reinterpret_cast<float2*>(g_Qp + (size_t)r0 * 256 + c) =
                        make_float2(acc[mt][nt][0], acc[mt][nt][1]);
                if (r0 + 8 < n)
                    *reinterpret_cast<float2*>(g_Qp + (size_t)(r0 + 8) * 256 + c) =
                        make_float2(acc[mt][nt][2], acc[mt][nt][3]);
            }
        }
    }
}

// ---------------- fused attention: 2-edge pipelined segment softmax ----------------
__global__ __launch_bounds__(256) void attn_kernel(const float* __restrict__ x, int n) {
    int r = (blockIdx.x << 3) + (threadIdx.x >> 5);
    if (r >= n) return;
    int lane = threadIdx.x & 31;
    int j = lane & 7;

    const float4* qr = reinterpret_cast<const float4*>(g_Qp + (size_t)r * 256);
    float4 q0 = qr[lane * 2], q1 = qr[lane * 2 + 1];

    int beg = g_rowptr[r], end = g_rowptr[r + 1];
    float dsum = 0.f;
    float4 a0 = make_float4(0.f, 0.f, 0.f, 0.f);
    float4 a1 = a0;

    int p = beg;
    for (; p + 1 < end; p += 2) {
        int s0 = g_esend[p], s1 = g_esend[p + 1];
        const float4* xs0 = reinterpret_cast<const float4*>(x + (size_t)s0 * 64);
        const float4* xs1 = reinterpret_cast<const float4*>(x + (size_t)s1 * 64);
        float4 u0 = xs0[j * 2], u1 = xs0[j * 2 + 1];
        float4 w0 = xs1[j * 2], w1 = xs1[j * 2 + 1];

        float pa = q0.x * u0.x + q0.y * u0.y + q0.z * u0.z + q0.w * u0.w
                 + q1.x * u1.x + q1.y * u1.y + q1.z * u1.z + q1.w * u1.w;
        float pb = q0.x * w0.x + q0.y * w0.y + q0.z * w0.z + q0.w * w0.w
                 + q1.x * w1.x + q1.y * w1.y + q1.z * w1.z + q1.w * w1.w;
        pa += __shfl_xor_sync(0xffffffffu, pa, 1);
        pb += __shfl_xor_sync(0xffffffffu, pb, 1);
        pa += __shfl_xor_sync(0xffffffffu, pa, 2);
        pb += __shfl_xor_sync(0xffffffffu, pb, 2);
        pa += __shfl_xor_sync(0xffffffffu, pa, 4);
        pb += __shfl_xor_sync(0xffffffffu, pb, 4);

        float ea = __expf(pa);
        float eb = __expf(pb);
        dsum += ea + eb;
        a0.x += ea * u0.x + eb * w0.x; a0.y += ea * u0.y + eb * w0.y;
        a0.z += ea * u0.z + eb * w0.z; a0.w += ea * u0.w + eb * w0.w;
        a1.x += ea * u1.x + eb * w1.x; a1.y += ea * u1.y + eb * w1.y;
        a1.z += ea * u1.z + eb * w1.z; a1.w += ea * u1.w + eb * w1.w;
    }
    if (p < end) {
        int s = g_esend[p];
        const float4* xs = reinterpret_cast<const float4*>(x + (size_t)s * 64);
        float4 u0 = xs[j * 2], u1 = xs[j * 2 + 1];
        float pa = q0.x * u0.x + q0.y * u0.y + q0.z * u0.z + q0.w * u0.w
                 + q1.x * u1.x + q1.y * u1.y + q1.z * u1.z + q1.w * u1.w;
        pa += __shfl_xor_sync(0xffffffffu, pa, 1);
        pa += __shfl_xor_sync(0xffffffffu, pa, 2);
        pa += __shfl_xor_sync(0xffffffffu, pa, 4);
        float ea = __expf(pa);
        dsum += ea;
        a0.x += ea * u0.x; a0.y += ea * u0.y; a0.z += ea * u0.z; a0.w += ea * u0.w;
        a1.x += ea * u1.x; a1.y += ea * u1.y; a1.z += ea * u1.z; a1.w += ea * u1.w;
    }

    float rinv = (dsum > 0.f) ? (1.0f / dsum) : 0.f;
    a0.x *= rinv; a0.y *= rinv; a0.z *= rinv; a0.w *= rinv;
    a1.x *= rinv; a1.y *= rinv; a1.z *= rinv; a1.w *= rinv;

    float4* tr = reinterpret_cast<float4*>(g_T + (size_t)r * 256);
    tr[lane * 2] = a0;
    tr[lane * 2 + 1] = a1;
}

// ---------------- GEMM 2: out = x + T @ Wst  (tensor cores, 3-term BF16) ----------------
__global__ __launch_bounds__(128) void gemm_out_kernel(const float* __restrict__ x,
                                                       float* __restrict__ out, int n) {
    __shared__ float As[128][68];
    int row0 = blockIdx.x * 128;
    int tid = threadIdx.x, warp = tid >> 5, lane = tid & 31;
    int rq = lane >> 2, rr = lane & 3;

    float acc[2][8][4];
    #pragma unroll
    for (int mt = 0; mt < 2; mt++)
        #pragma unroll
        for (int nt = 0; nt < 8; nt++)
            #pragma unroll
            for (int q = 0; q < 4; q++) acc[mt][nt][q] = 0.f;

    for (int kc = 0; kc < 4; kc++) {
        for (int i = tid; i < 2048; i += 128) {
            int r = i >> 4, k4 = (i & 15) << 2;
            int gr = row0 + r;
            float4 v = make_float4(0.f, 0.f, 0.f, 0.f);
            if (gr < n)
                v = *reinterpret_cast<const float4*>(g_T + (size_t)gr * 256 + kc * 64 + k4);
            *reinterpret_cast<float4*>(&As[r][k4]) = v;
        }
        __syncthreads();

        #pragma unroll
        for (int kt = 0; kt < 4; kt++) {
            int kb = (kt << 4) + rr * 2;
            unsigned ah[2][4], al[2][4];
            #pragma unroll
            for (int mt = 0; mt < 2; mt++)
                build_a_frags(As, (warp << 5) + (mt << 4) + rq, kb, ah[mt], al[mt]);

            const uint4* Bf = g_WstF + ((kc * 4 + kt) * 8) * 32 + lane;
            #pragma unroll
            for (int half = 0; half < 2; half++) {
                uint4 b[4];
                #pragma unroll
                for (int nt = 0; nt < 4; nt++) b[nt] = Bf[(half * 4 + nt) * 32];
                #pragma unroll
                for (int nt = 0; nt < 4; nt++)
                    #pragma unroll
                    for (int mt = 0; mt < 2; mt++)
                        MMA_BF16(acc[mt][half * 4 + nt],
                                 ah[mt][0], ah[mt][1], ah[mt][2], ah[mt][3],
                                 b[nt].x, b[nt].y);
                #pragma unroll
                for (int nt = 0; nt < 4; nt++)
                    #pragma unroll
                    for (int mt = 0; mt < 2; mt++)
                        MMA_BF16(acc[mt][half * 4 + nt],
                                 al[mt][0], al[mt][1], al[mt][2], al[mt][3],
                                 b[nt].x, b[nt].y);
                #pragma unroll
                for (int nt = 0; nt < 4; nt++)
                    #pragma unroll
                    for (int mt = 0; mt < 2; mt++)
                        MMA_BF16(acc[mt][half * 4 + nt],
                                 ah[mt][0], ah[mt][1], ah[mt][2], ah[mt][3],
                                 b[nt].z, b[nt].w);
            }
        }
        __syncthreads();
    }

    #pragma unroll
    for (int mt = 0; mt < 2; mt++) {
        int r0 = row0 + (warp << 5) + (mt << 4) + rq;
        #pragma unroll
        for (int nt = 0; nt < 8; nt++) {
            int c = nt * 8 + rr * 2;
            if (r0 < n) {
                float2 xv = *reinterpret_cast<const float2*>(x + (size_t)r0 * 64 + c);
                *reinterpret_cast<float2*>(out + (size_t)r0 * 64 + c) =
                    make_float2(acc[mt][nt][0] + xv.x, acc[mt][nt][1] + xv.y);
            }
            if (r0 + 8 < n) {
                float2 xv = *reinterpret_cast<const float2*>(x + (size_t)(r0 + 8) * 64 + c);
                *reinterpret_cast<float2*>(out + (size_t)(r0 + 8) * 64 + c) =
                    make_float2(acc[mt][nt][2] + xv.x, acc[mt][nt][3] + xv.y);
            }
        }
    }
}

// ---------------- launch ----------------
extern "C" void kernel_launch(void* const* d_in, const int* in_sizes, int n_in,
                              void* d_out, int out_size) {
    const float* x    = (const float*)d_in[0];
    const float* Wq   = (const float*)d_in[1];
    const float* Wk   = (const float*)d_in[2];
    const float* Wv   = (const float*)d_in[3];
    const float* Wout = (const float*)d_in[4];
    const int*   ei   = (const int*)d_in[5];

    int n = in_sizes[0] / FEAT;       // 50000
    int E = in_sizes[5] / 2;          // 400000
    const int* send = ei;
    const int* recv = ei + E;
    int nb = (n + 1023) / 1024;       // 49

    // Order keeps the profiler's fixed capture slot on gemm_qp.
    prep_mats_kernel<<<8, 256>>>(Wq, Wk, Wv, Wout);        // 1
    pack_frags_kernel<<<32, 256>>>();                      // 2
    zero_deg_kernel<<<(n + 511) / 512, 512>>>(n);          // 3
    gemm_qp_kernel<<<(n + 127) / 128, 128>>>(x, n);        // 4  <- profiled

    count_deg_kernel<<<(E + 511) / 512, 512>>>(recv, E);
    scan_blocks_kernel<<<nb, 1024>>>(n);
    scan_tops_kernel<<<1, 32>>>(nb, n);
    scan_add_kernel<<<nb, 1024>>>(n);
    scatter_edges_kernel<<<(E + 511) / 512, 512>>>(send, recv, E);

    attn_kernel<<<(n + 7) / 8, 256>>>(x, n);

    gemm_out_kernel<<<(n + 127) / 128, 128>>>(x, (float*)d_out, n);
}